// round 11
// baseline (speedup 1.0000x reference)
#include <cuda_runtime.h>
#include <cuda_fp16.h>
#include <cstdint>

#define N_NODES 100000
#define N_EDGES 1250000
#define D_IN 32
#define H 64
#define SCAN_B 1024
#define NB ((N_NODES + SCAN_B - 1) / SCAN_B)   // 98
#define NPW 8                                   // nodes per warp (MLP)
#define MLPB ((N_NODES + 8 * NPW - 1) / (8 * NPW))   // 1563 blocks

// scratch
__device__ __half g_hh[(size_t)N_NODES * H];    // fp16 copy of h (gather source)
__device__ int    g_deg[N_NODES];
__device__ int    g_off[N_NODES + 1];
__device__ int    g_pos[N_NODES];
__device__ int    g_csr_col[N_EDGES];
__device__ int    g_flag[NB];                   // decoupled-lookback: agg+1 (0 = not ready)

// ---- packed f32x2 helpers (sm_103a dual-FMA) --------------------------------
__device__ __forceinline__ unsigned long long pk2(float lo, float hi) {
    unsigned long long r;
    asm("mov.b64 %0, {%1, %2};" : "=l"(r) : "f"(lo), "f"(hi));
    return r;
}
__device__ __forceinline__ void upk2(unsigned long long v, float& lo, float& hi) {
    asm("mov.b64 {%0, %1}, %2;" : "=f"(lo), "=f"(hi) : "l"(v));
}
__device__ __forceinline__ void fma2(unsigned long long& d, unsigned long long a,
                                     unsigned long long b) {
    asm("fma.rn.f32x2 %0, %1, %2, %0;" : "+l"(d) : "l"(a), "l"(b));
}

// ---------------------------------------------------------------------------
// K1: fused node MLP, 8 nodes/warp, k-pair FFMA2.  (identical to R10)
// Writes h fp32 -> out (exact self term) and h fp16 -> g_hh (gather source).
// ---------------------------------------------------------------------------
__global__ __launch_bounds__(256) void mlp_kernel(
    const float* __restrict__ x,
    const float* __restrict__ W1, const float* __restrict__ b1,
    const float* __restrict__ g1, const float* __restrict__ be1,
    const float* __restrict__ W2, const float* __restrict__ b2,
    const float* __restrict__ g2, const float* __restrict__ be2,
    float* __restrict__ out)
{
    const int tid = threadIdx.x;

    __shared__ __align__(16) unsigned long long sW1p[(D_IN / 2) * H];   // 8 KB
    __shared__ __align__(16) unsigned long long sW2p[(H / 2) * H];      // 16 KB
    __shared__ float sb1[H], sg1[H], sbe1[H];
    __shared__ float sb2[H], sg2[H], sbe2[H];
    __shared__ __align__(16) float sx[8][NPW][D_IN];   // 8 KB
    __shared__ __align__(16) float sh[8][NPW][H];      // 16 KB

    {
        float* w1f = (float*)sW1p;
        float* w2f = (float*)sW2p;
        for (int i = tid; i < D_IN * H; i += 256) {
            int k = i >> 6, d = i & 63;
            w1f[((k >> 1) * 64 + d) * 2 + (k & 1)] = W1[i];
        }
        for (int i = tid; i < H * H; i += 256) {
            int k = i >> 6, d = i & 63;
            w2f[((k >> 1) * 64 + d) * 2 + (k & 1)] = W2[i];
        }
    }
    if (tid < H) {
        sb1[tid] = b1[tid]; sg1[tid] = g1[tid]; sbe1[tid] = be1[tid];
        sb2[tid] = b2[tid]; sg2[tid] = g2[tid]; sbe2[tid] = be2[tid];
    }
    __syncthreads();

    const int warp = tid >> 5;
    const int lane = tid & 31;
    const int n0 = (blockIdx.x * 8 + warp) * NPW;
    if (n0 >= N_NODES) return;

    #pragma unroll
    for (int j = 0; j < NPW; j++) {
        const int nj = min(n0 + j, N_NODES - 1);      // clamp (tail-safe)
        sx[warp][j][lane] = x[(size_t)nj * D_IN + lane];
    }
    __syncwarp();

    // ---- layer 1 ----
    unsigned long long a0[NPW], a1[NPW];
    #pragma unroll
    for (int j = 0; j < NPW; j++) {
        a0[j] = pk2(sb1[lane],      0.0f);
        a1[j] = pk2(sb1[lane + 32], 0.0f);
    }
    #pragma unroll
    for (int kp2 = 0; kp2 < D_IN / 4; kp2++) {
        const unsigned long long w0a = sW1p[(2 * kp2)     * 64 + lane];
        const unsigned long long w1a = sW1p[(2 * kp2)     * 64 + lane + 32];
        const unsigned long long w0b = sW1p[(2 * kp2 + 1) * 64 + lane];
        const unsigned long long w1b = sW1p[(2 * kp2 + 1) * 64 + lane + 32];
        #pragma unroll
        for (int j = 0; j < NPW; j++) {
            const double2 xd = *(const double2*)&sx[warp][j][kp2 * 4];
            const unsigned long long xlo = __double_as_longlong(xd.x);
            const unsigned long long xhi = __double_as_longlong(xd.y);
            fma2(a0[j], xlo, w0a);
            fma2(a1[j], xlo, w1a);
            fma2(a0[j], xhi, w0b);
            fma2(a1[j], xhi, w1b);
        }
    }
    #pragma unroll
    for (int g = 0; g < NPW; g += 4) {
        float s[4], q[4], v0[4], v1[4];
        #pragma unroll
        for (int u = 0; u < 4; u++) {
            float l0, h0, l1, h1;
            upk2(a0[g + u], l0, h0); upk2(a1[g + u], l1, h1);
            v0[u] = l0 + h0; v1[u] = l1 + h1;
            s[u] = v0[u] + v1[u];
            q[u] = v0[u] * v0[u] + v1[u] * v1[u];
        }
        #pragma unroll
        for (int off = 16; off > 0; off >>= 1) {
            #pragma unroll
            for (int u = 0; u < 4; u++) {
                s[u] += __shfl_xor_sync(0xffffffffu, s[u], off);
                q[u] += __shfl_xor_sync(0xffffffffu, q[u], off);
            }
        }
        #pragma unroll
        for (int u = 0; u < 4; u++) {
            const float mu  = s[u] * (1.0f / H);
            const float var = q[u] * (1.0f / H) - mu * mu;
            const float inv = rsqrtf(var + 1e-5f);
            float r0 = (v0[u] - mu) * inv * sg1[lane]      + sbe1[lane];
            float r1 = (v1[u] - mu) * inv * sg1[lane + 32] + sbe1[lane + 32];
            sh[warp][g + u][lane]      = fmaxf(r0, 0.0f);
            sh[warp][g + u][lane + 32] = fmaxf(r1, 0.0f);
        }
    }
    __syncwarp();

    // ---- layer 2 ----
    unsigned long long c0[NPW], c1[NPW];
    #pragma unroll
    for (int j = 0; j < NPW; j++) {
        c0[j] = pk2(sb2[lane],      0.0f);
        c1[j] = pk2(sb2[lane + 32], 0.0f);
    }
    #pragma unroll
    for (int kp2 = 0; kp2 < H / 4; kp2++) {
        const unsigned long long w0a = sW2p[(2 * kp2)     * 64 + lane];
        const unsigned long long w1a = sW2p[(2 * kp2)     * 64 + lane + 32];
        const unsigned long long w0b = sW2p[(2 * kp2 + 1) * 64 + lane];
        const unsigned long long w1b = sW2p[(2 * kp2 + 1) * 64 + lane + 32];
        #pragma unroll
        for (int j = 0; j < NPW; j++) {
            const double2 hd = *(const double2*)&sh[warp][j][kp2 * 4];
            const unsigned long long hlo = __double_as_longlong(hd.x);
            const unsigned long long hhi = __double_as_longlong(hd.y);
            fma2(c0[j], hlo, w0a);
            fma2(c1[j], hlo, w1a);
            fma2(c0[j], hhi, w0b);
            fma2(c1[j], hhi, w1b);
        }
    }
    #pragma unroll
    for (int g = 0; g < NPW; g += 4) {
        float s[4], q[4], v0[4], v1[4];
        #pragma unroll
        for (int u = 0; u < 4; u++) {
            float l0, h0, l1, h1;
            upk2(c0[g + u], l0, h0); upk2(c1[g + u], l1, h1);
            v0[u] = l0 + h0; v1[u] = l1 + h1;
            s[u] = v0[u] + v1[u];
            q[u] = v0[u] * v0[u] + v1[u] * v1[u];
        }
        #pragma unroll
        for (int off = 16; off > 0; off >>= 1) {
            #pragma unroll
            for (int u = 0; u < 4; u++) {
                s[u] += __shfl_xor_sync(0xffffffffu, s[u], off);
                q[u] += __shfl_xor_sync(0xffffffffu, q[u], off);
            }
        }
        #pragma unroll
        for (int u = 0; u < 4; u++) {
            const int nj = n0 + g + u;
            if (nj < N_NODES) {
                const float mu  = s[u] * (1.0f / H);
                const float var = q[u] * (1.0f / H) - mu * mu;
                const float inv = rsqrtf(var + 1e-5f);
                float r0 = (v0[u] - mu) * inv * sg2[lane]      + sbe2[lane];
                float r1 = (v1[u] - mu) * inv * sg2[lane + 32] + sbe2[lane + 32];
                r0 = fmaxf(r0, 0.0f);
                r1 = fmaxf(r1, 0.0f);
                const size_t base = (size_t)nj * H;
                out[base + lane]       = r0;               // exact self term
                out[base + lane + 32]  = r1;
                g_hh[base + lane]      = __float2half(r0); // fp16 gather source
                g_hh[base + lane + 32] = __float2half(r1);
            }
        }
    }
}

// ---------------------------------------------------------------------------
// K2b: degree histogram (4 edges/thread, int4 loads, fire-and-forget atomics)
// ---------------------------------------------------------------------------
__global__ __launch_bounds__(256) void hist_kernel(const int* __restrict__ ei)
{
    const int e4 = (blockIdx.x * 256 + threadIdx.x) * 4;
    if (e4 >= N_EDGES) return;
    const int4 rows = *(const int4*)&ei[e4];
    #pragma unroll
    for (int j = 0; j < 4; j++) {
        const int row = (&rows.x)[j];
        if ((unsigned)row < N_NODES) atomicAdd(&g_deg[row], 1);
    }
}

// ---------------------------------------------------------------------------
// K3b: single-kernel exclusive scan (decoupled lookback; 98 blocks all wave-1)
// ---------------------------------------------------------------------------
__global__ __launch_bounds__(SCAN_B) void scan_kernel()
{
    __shared__ int wsum[32];
    __shared__ int sprefix;
    const int t   = threadIdx.x;
    const int bid = blockIdx.x;
    const int i   = bid * SCAN_B + t;

    int v = (i < N_NODES) ? g_deg[i] : 0;
    const int orig = v;
    #pragma unroll
    for (int o = 1; o < 32; o <<= 1) {
        int n = __shfl_up_sync(0xffffffffu, v, o);
        if ((t & 31) >= o) v += n;
    }
    if ((t & 31) == 31) wsum[t >> 5] = v;
    __syncthreads();
    if (t < 32) {
        int w = wsum[t];
        #pragma unroll
        for (int o = 1; o < 32; o <<= 1) {
            int n = __shfl_up_sync(0xffffffffu, w, o);
            if (t >= o) w += n;
        }
        wsum[t] = w;
    }
    __syncthreads();
    const int base = (t >= 32) ? wsum[(t >> 5) - 1] : 0;
    const int incl = v + base;

    if (t == SCAN_B - 1) ((volatile int*)g_flag)[bid] = incl + 1;

    if (t < 32) {
        int sum = 0;
        for (int j0 = bid - 1; j0 >= 0; j0 -= 32) {
            const int j = j0 - t;
            int av = 0;
            if (j >= 0) {
                while ((av = ((volatile int*)g_flag)[j]) == 0) {}
                av -= 1;
            }
            #pragma unroll
            for (int o = 16; o > 0; o >>= 1)
                av += __shfl_xor_sync(0xffffffffu, av, o);
            sum += av;
        }
        if (t == 0) sprefix = sum;
    }
    __syncthreads();

    if (i < N_NODES) {
        const int o = sprefix + incl - orig;
        g_off[i] = o;
        g_pos[i] = o;
    }
    if (i == 0) g_off[N_NODES] = N_EDGES;
}

// ---------------------------------------------------------------------------
// K4b: scatter column ids into CSR slots (4 edges/thread, int4 index loads)
// ---------------------------------------------------------------------------
__global__ __launch_bounds__(256) void scatter_kernel(const int* __restrict__ ei)
{
    const int e4 = (blockIdx.x * 256 + threadIdx.x) * 4;
    if (e4 >= N_EDGES) return;
    const int4 rows = *(const int4*)&ei[e4];
    const int4 cols = *(const int4*)&ei[N_EDGES + e4];
    #pragma unroll
    for (int j = 0; j < 4; j++) {
        const int row = (&rows.x)[j];
        const int col = (&cols.x)[j];
        if ((unsigned)row < N_NODES) {
            int p = atomicAdd(&g_pos[row], 1);
            g_csr_col[p] = col;
        }
    }
}

// ---------------------------------------------------------------------------
// K5: pull-gather v3 — warp per node, QUARTER-WARP per edge.
// fp16 row = 128B = 8 lanes x uint4; 4 edges per warp-instruction group:
// per 4 edges = 1 SHFL.IDX + 1 setp + 1 LDG.128 + 8 cvt + 8 FADD.
// Quarter q handles edges t0+q; lane ql covers dims ql*8..ql*8+7.
// ---------------------------------------------------------------------------
__global__ __launch_bounds__(256) void gather_kernel(float* __restrict__ out)
{
    const int n = blockIdx.x * 8 + (threadIdx.x >> 5);
    if (n >= N_NODES) return;
    const int lane = threadIdx.x & 31;
    const int q  = lane >> 3;       // quarter 0..3 -> edge slot
    const int ql = lane & 7;        // position within quarter -> dim chunk

    float2 a0 = {0.f, 0.f}, a1 = {0.f, 0.f}, a2 = {0.f, 0.f}, a3 = {0.f, 0.f};

    const int start = g_off[n];
    const int end   = g_off[n + 1];

    for (int jb = start; jb < end; jb += 32) {
        const int cnt = min(32, end - jb);
        int cidx = (lane < cnt) ? g_csr_col[jb + lane] : 0;
        for (int t0 = 0; t0 < cnt; t0 += 4) {
            const int tt = t0 + q;
            const int cc = __shfl_sync(0xffffffffu, cidx, tt & 31);
            if (tt < cnt) {
                const uint4 u = __ldg((const uint4*)(g_hh + (size_t)cc * H) + ql);
                float2 f;
                f = __half22float2(*(const half2*)&u.x); a0.x += f.x; a0.y += f.y;
                f = __half22float2(*(const half2*)&u.y); a1.x += f.x; a1.y += f.y;
                f = __half22float2(*(const half2*)&u.z); a2.x += f.x; a2.y += f.y;
                f = __half22float2(*(const half2*)&u.w); a3.x += f.x; a3.y += f.y;
            }
        }
    }

    // reduce across quarters (same ql): xor by 8 then 16
    #pragma unroll
    for (int off = 8; off <= 16; off <<= 1) {
        a0.x += __shfl_xor_sync(0xffffffffu, a0.x, off);
        a0.y += __shfl_xor_sync(0xffffffffu, a0.y, off);
        a1.x += __shfl_xor_sync(0xffffffffu, a1.x, off);
        a1.y += __shfl_xor_sync(0xffffffffu, a1.y, off);
        a2.x += __shfl_xor_sync(0xffffffffu, a2.x, off);
        a2.y += __shfl_xor_sync(0xffffffffu, a2.y, off);
        a3.x += __shfl_xor_sync(0xffffffffu, a3.x, off);
        a3.y += __shfl_xor_sync(0xffffffffu, a3.y, off);
    }

    if (lane < 8) {   // q == 0 holds full sums; lane ql owns dims ql*8..+7
        float4* op = (float4*)(out + (size_t)n * H + ql * 8);
        const float4 s0 = op[0];   // exact fp32 self term (written by MLP)
        const float4 s1 = op[1];
        op[0] = make_float4(s0.x + a0.x, s0.y + a0.y, s0.z + a1.x, s0.w + a1.y);
        op[1] = make_float4(s1.x + a2.x, s1.y + a2.y, s1.z + a3.x, s1.w + a3.y);
    }
}

// ---------------------------------------------------------------------------
// inputs: x, edge_index(int32 [2,E]), W1, b1, g1, beta1, W2, b2, g2, beta2
// Two-stream fork inside graph capture: MLP on capture stream, CSR build on s2.
// ---------------------------------------------------------------------------
extern "C" void kernel_launch(void* const* d_in, const int* in_sizes, int n_in,
                              void* d_out, int out_size)
{
    const float* x   = (const float*)d_in[0];
    const int*   ei  = (const int*)d_in[1];
    const float* W1  = (const float*)d_in[2];
    const float* b1  = (const float*)d_in[3];
    const float* g1  = (const float*)d_in[4];
    const float* be1 = (const float*)d_in[5];
    const float* W2  = (const float*)d_in[6];
    const float* b2  = (const float*)d_in[7];
    const float* g2  = (const float*)d_in[8];
    const float* be2 = (const float*)d_in[9];
    float* out = (float*)d_out;

    static cudaStream_t s2 = nullptr;
    static cudaEvent_t evFork = nullptr, evJoin = nullptr;
    static void* p_deg = nullptr;
    static void* p_flag = nullptr;
    if (!s2) {
        cudaStreamCreateWithFlags(&s2, cudaStreamNonBlocking);
        cudaEventCreateWithFlags(&evFork, cudaEventDisableTiming);
        cudaEventCreateWithFlags(&evJoin, cudaEventDisableTiming);
        cudaGetSymbolAddress(&p_deg,  g_deg);
        cudaGetSymbolAddress(&p_flag, g_flag);
    }

    cudaEventRecord(evFork, 0);
    cudaStreamWaitEvent(s2, evFork, 0);

    cudaMemsetAsync(p_deg,  0, sizeof(int) * N_NODES, s2);
    cudaMemsetAsync(p_flag, 0, sizeof(int) * NB, s2);
    hist_kernel<<<(N_EDGES / 4 + 255) / 256, 256, 0, s2>>>(ei);
    scan_kernel<<<NB, SCAN_B, 0, s2>>>();
    scatter_kernel<<<(N_EDGES / 4 + 255) / 256, 256, 0, s2>>>(ei);
    cudaEventRecord(evJoin, s2);

    mlp_kernel<<<MLPB, 256>>>(x, W1, b1, g1, be1, W2, b2, g2, be2, out);

    cudaStreamWaitEvent(0, evJoin, 0);
    gather_kernel<<<(N_NODES + 7) / 8, 256>>>(out);
}

// round 12
// speedup vs baseline: 1.0224x; 1.0224x over previous
#include <cuda_runtime.h>
#include <cuda_fp16.h>
#include <cstdint>

#define N_NODES 100000
#define N_EDGES 1250000
#define D_IN 32
#define H 64
#define SCAN_B 1024
#define NB ((N_NODES + SCAN_B - 1) / SCAN_B)   // 98
#define NPW 8                                   // nodes per warp (MLP)
#define MLPB ((N_NODES + 8 * NPW - 1) / (8 * NPW))   // 1563 blocks

// scratch
__device__ __half g_hh[(size_t)N_NODES * H];    // fp16 copy of h (gather source)
__device__ int    g_deg[N_NODES];
__device__ int    g_off[N_NODES + 1];
__device__ int    g_pos[N_NODES];
__device__ int    g_csr_col[N_EDGES];
__device__ int    g_flag[NB];                   // decoupled-lookback: agg+1 (0 = not ready)

// ---- packed f32x2 helpers (sm_103a dual-FMA) --------------------------------
__device__ __forceinline__ unsigned long long pk2(float lo, float hi) {
    unsigned long long r;
    asm("mov.b64 %0, {%1, %2};" : "=l"(r) : "f"(lo), "f"(hi));
    return r;
}
__device__ __forceinline__ void upk2(unsigned long long v, float& lo, float& hi) {
    asm("mov.b64 {%0, %1}, %2;" : "=f"(lo), "=f"(hi) : "l"(v));
}
__device__ __forceinline__ void fma2(unsigned long long& d, unsigned long long a,
                                     unsigned long long b) {
    asm("fma.rn.f32x2 %0, %1, %2, %0;" : "+l"(d) : "l"(a), "l"(b));
}

// ---------------------------------------------------------------------------
// K1: fused node MLP, 8 nodes/warp, k-pair FFMA2.
// __launch_bounds__(256, 4): force 64 regs -> 4 blocks/SM (occ 37.5% -> 50%).
// Writes h fp32 -> out (exact self term) and h fp16 -> g_hh (gather source).
// ---------------------------------------------------------------------------
__global__ __launch_bounds__(256, 4) void mlp_kernel(
    const float* __restrict__ x,
    const float* __restrict__ W1, const float* __restrict__ b1,
    const float* __restrict__ g1, const float* __restrict__ be1,
    const float* __restrict__ W2, const float* __restrict__ b2,
    const float* __restrict__ g2, const float* __restrict__ be2,
    float* __restrict__ out)
{
    const int tid = threadIdx.x;

    __shared__ __align__(16) unsigned long long sW1p[(D_IN / 2) * H];   // 8 KB
    __shared__ __align__(16) unsigned long long sW2p[(H / 2) * H];      // 16 KB
    __shared__ float sb1[H], sg1[H], sbe1[H];
    __shared__ float sb2[H], sg2[H], sbe2[H];
    __shared__ __align__(16) float sx[8][NPW][D_IN];   // 8 KB
    __shared__ __align__(16) float sh[8][NPW][H];      // 16 KB

    {
        float* w1f = (float*)sW1p;
        float* w2f = (float*)sW2p;
        for (int i = tid; i < D_IN * H; i += 256) {
            int k = i >> 6, d = i & 63;
            w1f[((k >> 1) * 64 + d) * 2 + (k & 1)] = W1[i];
        }
        for (int i = tid; i < H * H; i += 256) {
            int k = i >> 6, d = i & 63;
            w2f[((k >> 1) * 64 + d) * 2 + (k & 1)] = W2[i];
        }
    }
    if (tid < H) {
        sb1[tid] = b1[tid]; sg1[tid] = g1[tid]; sbe1[tid] = be1[tid];
        sb2[tid] = b2[tid]; sg2[tid] = g2[tid]; sbe2[tid] = be2[tid];
    }
    __syncthreads();

    const int warp = tid >> 5;
    const int lane = tid & 31;
    const int n0 = (blockIdx.x * 8 + warp) * NPW;
    if (n0 >= N_NODES) return;

    #pragma unroll
    for (int j = 0; j < NPW; j++) {
        const int nj = min(n0 + j, N_NODES - 1);      // clamp (tail-safe)
        sx[warp][j][lane] = x[(size_t)nj * D_IN + lane];
    }
    __syncwarp();

    // ---- layer 1 ----
    unsigned long long a0[NPW], a1[NPW];
    #pragma unroll
    for (int j = 0; j < NPW; j++) {
        a0[j] = pk2(sb1[lane],      0.0f);
        a1[j] = pk2(sb1[lane + 32], 0.0f);
    }
    #pragma unroll
    for (int kp2 = 0; kp2 < D_IN / 4; kp2++) {
        const unsigned long long w0a = sW1p[(2 * kp2)     * 64 + lane];
        const unsigned long long w1a = sW1p[(2 * kp2)     * 64 + lane + 32];
        const unsigned long long w0b = sW1p[(2 * kp2 + 1) * 64 + lane];
        const unsigned long long w1b = sW1p[(2 * kp2 + 1) * 64 + lane + 32];
        #pragma unroll
        for (int j = 0; j < NPW; j++) {
            const double2 xd = *(const double2*)&sx[warp][j][kp2 * 4];
            const unsigned long long xlo = __double_as_longlong(xd.x);
            const unsigned long long xhi = __double_as_longlong(xd.y);
            fma2(a0[j], xlo, w0a);
            fma2(a1[j], xlo, w1a);
            fma2(a0[j], xhi, w0b);
            fma2(a1[j], xhi, w1b);
        }
    }
    #pragma unroll
    for (int g = 0; g < NPW; g += 4) {
        float s[4], q[4], v0[4], v1[4];
        #pragma unroll
        for (int u = 0; u < 4; u++) {
            float l0, h0, l1, h1;
            upk2(a0[g + u], l0, h0); upk2(a1[g + u], l1, h1);
            v0[u] = l0 + h0; v1[u] = l1 + h1;
            s[u] = v0[u] + v1[u];
            q[u] = v0[u] * v0[u] + v1[u] * v1[u];
        }
        #pragma unroll
        for (int off = 16; off > 0; off >>= 1) {
            #pragma unroll
            for (int u = 0; u < 4; u++) {
                s[u] += __shfl_xor_sync(0xffffffffu, s[u], off);
                q[u] += __shfl_xor_sync(0xffffffffu, q[u], off);
            }
        }
        #pragma unroll
        for (int u = 0; u < 4; u++) {
            const float mu  = s[u] * (1.0f / H);
            const float var = q[u] * (1.0f / H) - mu * mu;
            const float inv = rsqrtf(var + 1e-5f);
            float r0 = (v0[u] - mu) * inv * sg1[lane]      + sbe1[lane];
            float r1 = (v1[u] - mu) * inv * sg1[lane + 32] + sbe1[lane + 32];
            sh[warp][g + u][lane]      = fmaxf(r0, 0.0f);
            sh[warp][g + u][lane + 32] = fmaxf(r1, 0.0f);
        }
    }
    __syncwarp();

    // ---- layer 2 ----
    unsigned long long c0[NPW], c1[NPW];
    #pragma unroll
    for (int j = 0; j < NPW; j++) {
        c0[j] = pk2(sb2[lane],      0.0f);
        c1[j] = pk2(sb2[lane + 32], 0.0f);
    }
    #pragma unroll
    for (int kp2 = 0; kp2 < H / 4; kp2++) {
        const unsigned long long w0a = sW2p[(2 * kp2)     * 64 + lane];
        const unsigned long long w1a = sW2p[(2 * kp2)     * 64 + lane + 32];
        const unsigned long long w0b = sW2p[(2 * kp2 + 1) * 64 + lane];
        const unsigned long long w1b = sW2p[(2 * kp2 + 1) * 64 + lane + 32];
        #pragma unroll
        for (int j = 0; j < NPW; j++) {
            const double2 hd = *(const double2*)&sh[warp][j][kp2 * 4];
            const unsigned long long hlo = __double_as_longlong(hd.x);
            const unsigned long long hhi = __double_as_longlong(hd.y);
            fma2(c0[j], hlo, w0a);
            fma2(c1[j], hlo, w1a);
            fma2(c0[j], hhi, w0b);
            fma2(c1[j], hhi, w1b);
        }
    }
    #pragma unroll
    for (int g = 0; g < NPW; g += 4) {
        float s[4], q[4], v0[4], v1[4];
        #pragma unroll
        for (int u = 0; u < 4; u++) {
            float l0, h0, l1, h1;
            upk2(c0[g + u], l0, h0); upk2(c1[g + u], l1, h1);
            v0[u] = l0 + h0; v1[u] = l1 + h1;
            s[u] = v0[u] + v1[u];
            q[u] = v0[u] * v0[u] + v1[u] * v1[u];
        }
        #pragma unroll
        for (int off = 16; off > 0; off >>= 1) {
            #pragma unroll
            for (int u = 0; u < 4; u++) {
                s[u] += __shfl_xor_sync(0xffffffffu, s[u], off);
                q[u] += __shfl_xor_sync(0xffffffffu, q[u], off);
            }
        }
        #pragma unroll
        for (int u = 0; u < 4; u++) {
            const int nj = n0 + g + u;
            if (nj < N_NODES) {
                const float mu  = s[u] * (1.0f / H);
                const float var = q[u] * (1.0f / H) - mu * mu;
                const float inv = rsqrtf(var + 1e-5f);
                float r0 = (v0[u] - mu) * inv * sg2[lane]      + sbe2[lane];
                float r1 = (v1[u] - mu) * inv * sg2[lane + 32] + sbe2[lane + 32];
                r0 = fmaxf(r0, 0.0f);
                r1 = fmaxf(r1, 0.0f);
                const size_t base = (size_t)nj * H;
                out[base + lane]       = r0;               // exact self term
                out[base + lane + 32]  = r1;
                g_hh[base + lane]      = __float2half(r0); // fp16 gather source
                g_hh[base + lane + 32] = __float2half(r1);
            }
        }
    }
}

// ---------------------------------------------------------------------------
// K2b: degree histogram (4 edges/thread, int4 loads, fire-and-forget atomics)
// ---------------------------------------------------------------------------
__global__ __launch_bounds__(256) void hist_kernel(const int* __restrict__ ei)
{
    const int e4 = (blockIdx.x * 256 + threadIdx.x) * 4;
    if (e4 >= N_EDGES) return;
    const int4 rows = *(const int4*)&ei[e4];
    #pragma unroll
    for (int j = 0; j < 4; j++) {
        const int row = (&rows.x)[j];
        if ((unsigned)row < N_NODES) atomicAdd(&g_deg[row], 1);
    }
}

// ---------------------------------------------------------------------------
// K3b: single-kernel exclusive scan (decoupled lookback; 98 blocks all wave-1)
// ---------------------------------------------------------------------------
__global__ __launch_bounds__(SCAN_B) void scan_kernel()
{
    __shared__ int wsum[32];
    __shared__ int sprefix;
    const int t   = threadIdx.x;
    const int bid = blockIdx.x;
    const int i   = bid * SCAN_B + t;

    int v = (i < N_NODES) ? g_deg[i] : 0;
    const int orig = v;
    #pragma unroll
    for (int o = 1; o < 32; o <<= 1) {
        int n = __shfl_up_sync(0xffffffffu, v, o);
        if ((t & 31) >= o) v += n;
    }
    if ((t & 31) == 31) wsum[t >> 5] = v;
    __syncthreads();
    if (t < 32) {
        int w = wsum[t];
        #pragma unroll
        for (int o = 1; o < 32; o <<= 1) {
            int n = __shfl_up_sync(0xffffffffu, w, o);
            if (t >= o) w += n;
        }
        wsum[t] = w;
    }
    __syncthreads();
    const int base = (t >= 32) ? wsum[(t >> 5) - 1] : 0;
    const int incl = v + base;

    if (t == SCAN_B - 1) ((volatile int*)g_flag)[bid] = incl + 1;

    if (t < 32) {
        int sum = 0;
        for (int j0 = bid - 1; j0 >= 0; j0 -= 32) {
            const int j = j0 - t;
            int av = 0;
            if (j >= 0) {
                while ((av = ((volatile int*)g_flag)[j]) == 0) {}
                av -= 1;
            }
            #pragma unroll
            for (int o = 16; o > 0; o >>= 1)
                av += __shfl_xor_sync(0xffffffffu, av, o);
            sum += av;
        }
        if (t == 0) sprefix = sum;
    }
    __syncthreads();

    if (i < N_NODES) {
        const int o = sprefix + incl - orig;
        g_off[i] = o;
        g_pos[i] = o;
    }
    if (i == 0) g_off[N_NODES] = N_EDGES;
}

// ---------------------------------------------------------------------------
// K4b: scatter column ids into CSR slots (4 edges/thread, int4 index loads)
// ---------------------------------------------------------------------------
__global__ __launch_bounds__(256) void scatter_kernel(const int* __restrict__ ei)
{
    const int e4 = (blockIdx.x * 256 + threadIdx.x) * 4;
    if (e4 >= N_EDGES) return;
    const int4 rows = *(const int4*)&ei[e4];
    const int4 cols = *(const int4*)&ei[N_EDGES + e4];
    #pragma unroll
    for (int j = 0; j < 4; j++) {
        const int row = (&rows.x)[j];
        const int col = (&cols.x)[j];
        if ((unsigned)row < N_NODES) {
            int p = atomicAdd(&g_pos[row], 1);
            g_csr_col[p] = col;
        }
    }
}

// ---------------------------------------------------------------------------
// K5: pull-gather — warp per node, quarter-warp per edge (R11 structure).
// ---------------------------------------------------------------------------
__global__ __launch_bounds__(256) void gather_kernel(float* __restrict__ out)
{
    const int n = blockIdx.x * 8 + (threadIdx.x >> 5);
    if (n >= N_NODES) return;
    const int lane = threadIdx.x & 31;
    const int q  = lane >> 3;       // quarter 0..3 -> edge slot
    const int ql = lane & 7;        // position within quarter -> dim chunk

    float2 a0 = {0.f, 0.f}, a1 = {0.f, 0.f}, a2 = {0.f, 0.f}, a3 = {0.f, 0.f};

    const int start = g_off[n];
    const int end   = g_off[n + 1];

    for (int jb = start; jb < end; jb += 32) {
        const int cnt = min(32, end - jb);
        int cidx = (lane < cnt) ? g_csr_col[jb + lane] : 0;
        for (int t0 = 0; t0 < cnt; t0 += 4) {
            const int tt = t0 + q;
            const int cc = __shfl_sync(0xffffffffu, cidx, tt & 31);
            if (tt < cnt) {
                const uint4 u = __ldg((const uint4*)(g_hh + (size_t)cc * H) + ql);
                float2 f;
                f = __half22float2(*(const half2*)&u.x); a0.x += f.x; a0.y += f.y;
                f = __half22float2(*(const half2*)&u.y); a1.x += f.x; a1.y += f.y;
                f = __half22float2(*(const half2*)&u.z); a2.x += f.x; a2.y += f.y;
                f = __half22float2(*(const half2*)&u.w); a3.x += f.x; a3.y += f.y;
            }
        }
    }

    #pragma unroll
    for (int off = 8; off <= 16; off <<= 1) {
        a0.x += __shfl_xor_sync(0xffffffffu, a0.x, off);
        a0.y += __shfl_xor_sync(0xffffffffu, a0.y, off);
        a1.x += __shfl_xor_sync(0xffffffffu, a1.x, off);
        a1.y += __shfl_xor_sync(0xffffffffu, a1.y, off);
        a2.x += __shfl_xor_sync(0xffffffffu, a2.x, off);
        a2.y += __shfl_xor_sync(0xffffffffu, a2.y, off);
        a3.x += __shfl_xor_sync(0xffffffffu, a3.x, off);
        a3.y += __shfl_xor_sync(0xffffffffu, a3.y, off);
    }

    if (lane < 8) {   // q == 0 holds full sums; lane ql owns dims ql*8..+7
        float4* op = (float4*)(out + (size_t)n * H + ql * 8);
        const float4 s0 = op[0];   // exact fp32 self term (written by MLP)
        const float4 s1 = op[1];
        op[0] = make_float4(s0.x + a0.x, s0.y + a0.y, s0.z + a1.x, s0.w + a1.y);
        op[1] = make_float4(s1.x + a2.x, s1.y + a2.y, s1.z + a3.x, s1.w + a3.y);
    }
}

// ---------------------------------------------------------------------------
// inputs: x, edge_index(int32 [2,E]), W1, b1, g1, beta1, W2, b2, g2, beta2
// Two-stream fork inside graph capture: MLP on capture stream, CSR build on s2.
// ---------------------------------------------------------------------------
extern "C" void kernel_launch(void* const* d_in, const int* in_sizes, int n_in,
                              void* d_out, int out_size)
{
    const float* x   = (const float*)d_in[0];
    const int*   ei  = (const int*)d_in[1];
    const float* W1  = (const float*)d_in[2];
    const float* b1  = (const float*)d_in[3];
    const float* g1  = (const float*)d_in[4];
    const float* be1 = (const float*)d_in[5];
    const float* W2  = (const float*)d_in[6];
    const float* b2  = (const float*)d_in[7];
    const float* g2  = (const float*)d_in[8];
    const float* be2 = (const float*)d_in[9];
    float* out = (float*)d_out;

    static cudaStream_t s2 = nullptr;
    static cudaEvent_t evFork = nullptr, evJoin = nullptr;
    static void* p_deg = nullptr;
    static void* p_flag = nullptr;
    if (!s2) {
        cudaStreamCreateWithFlags(&s2, cudaStreamNonBlocking);
        cudaEventCreateWithFlags(&evFork, cudaEventDisableTiming);
        cudaEventCreateWithFlags(&evJoin, cudaEventDisableTiming);
        cudaGetSymbolAddress(&p_deg,  g_deg);
        cudaGetSymbolAddress(&p_flag, g_flag);
    }

    cudaEventRecord(evFork, 0);
    cudaStreamWaitEvent(s2, evFork, 0);

    cudaMemsetAsync(p_deg,  0, sizeof(int) * N_NODES, s2);
    cudaMemsetAsync(p_flag, 0, sizeof(int) * NB, s2);
    hist_kernel<<<(N_EDGES / 4 + 255) / 256, 256, 0, s2>>>(ei);
    scan_kernel<<<NB, SCAN_B, 0, s2>>>();
    scatter_kernel<<<(N_EDGES / 4 + 255) / 256, 256, 0, s2>>>(ei);
    cudaEventRecord(evJoin, s2);

    mlp_kernel<<<MLPB, 256>>>(x, W1, b1, g1, be1, W2, b2, g2, be2, out);

    cudaStreamWaitEvent(0, evJoin, 0);
    gather_kernel<<<(N_NODES + 7) / 8, 256>>>(out);
}

// round 13
// speedup vs baseline: 1.1364x; 1.1115x over previous
#include <cuda_runtime.h>
#include <cuda_fp16.h>
#include <cstdint>

#define N_NODES 100000
#define N_EDGES 1250000
#define D_IN 32
#define H 64
#define SCAN_B 1024
#define NB ((N_NODES + SCAN_B - 1) / SCAN_B)   // 98
#define MB 128                                  // nodes per block (MLP)
#define MLPB ((N_NODES + MB - 1) / MB)          // 782 blocks

// SMEM layout (bytes) for mlp_kernel
#define OFF_X   0                               // uint32 tf32 [128][36]
#define OFF_W1  (OFF_X  + 128 * 36 * 4)         // uint32 tf32 Wt1 [64][36]
#define OFF_W2  (OFF_W1 + 64 * 36 * 4)          // uint32 tf32 Wt2 [64][68]
#define OFF_H   (OFF_W2 + 64 * 68 * 4)          // tf32 then fp32 [128][68]
#define OFF_P   (OFF_H  + 128 * 68 * 4)         // 6 x 64 fp32 params
#define SMEM_TOTAL (OFF_P + 6 * 64 * 4)

// scratch
__device__ __half g_hh[(size_t)N_NODES * H];    // fp16 copy of h (gather source)
__device__ int    g_deg[N_NODES];
__device__ int    g_off[N_NODES + 1];
__device__ int    g_pos[N_NODES];
__device__ int    g_csr_col[N_EDGES];
__device__ int    g_flag[NB];                   // decoupled-lookback: agg+1 (0 = not ready)

__device__ __forceinline__ uint32_t f2tf(float f) {
    uint32_t r;
    asm("cvt.rna.tf32.f32 %0, %1;" : "=r"(r) : "f"(f));
    return r;
}

__device__ __forceinline__ void mma_tf32(float* c, uint32_t a0, uint32_t a1,
                                         uint32_t a2, uint32_t a3,
                                         uint32_t b0, uint32_t b1) {
    asm volatile(
        "mma.sync.aligned.m16n8k8.row.col.f32.tf32.tf32.f32 "
        "{%0,%1,%2,%3}, {%4,%5,%6,%7}, {%8,%9}, {%0,%1,%2,%3};"
        : "+f"(c[0]), "+f"(c[1]), "+f"(c[2]), "+f"(c[3])
        : "r"(a0), "r"(a1), "r"(a2), "r"(a3), "r"(b0), "r"(b1));
}

// ---------------------------------------------------------------------------
// K1: tensor-core MLP.  Block = 128 nodes, 8 warps, warp = m16 row tile.
// Layer l: C = A @ W via m16n8k8 tf32 mma; LN in-fragment (quad shfl);
// restage as tf32 A operand; layer2; LN2; staged coalesced output.
// A-frag: a0=(r,c) a1=(r+8,c) a2=(r,c+4) a3=(r+8,c+4), r=l>>2, c=l&3
// B-frag: b0=W[k=c][n=l>>2], b1=W[k=c+4][n=l>>2]   (Wt[n][k] in SMEM)
// C-frag: c0=(r,2c) c1=(r,2c+1) c2=(r+8,2c) c3=(r+8,2c+1)
// ---------------------------------------------------------------------------
__global__ __launch_bounds__(256, 2) void mlp_kernel(
    const float* __restrict__ x,
    const float* __restrict__ W1, const float* __restrict__ b1,
    const float* __restrict__ g1, const float* __restrict__ be1,
    const float* __restrict__ W2, const float* __restrict__ b2,
    const float* __restrict__ g2, const float* __restrict__ be2,
    float* __restrict__ out)
{
    extern __shared__ char smem[];
    uint32_t* sX   = (uint32_t*)(smem + OFF_X);    // [128][36]
    uint32_t* sW1t = (uint32_t*)(smem + OFF_W1);   // [64][36]  Wt1[n][k]
    uint32_t* sW2t = (uint32_t*)(smem + OFF_W2);   // [64][68]  Wt2[n][k]
    uint32_t* sHu  = (uint32_t*)(smem + OFF_H);    // [128][68] tf32 h1
    float*    sHf  = (float*)   (smem + OFF_H);    // reused as fp32 out staging
    float*    sb1  = (float*)(smem + OFF_P);
    float*    sg1  = sb1 + 64;
    float*    sbe1 = sb1 + 128;
    float*    sb2  = sb1 + 192;
    float*    sg2  = sb1 + 256;
    float*    sbe2 = sb1 + 320;

    const int tid = threadIdx.x;
    const int base = blockIdx.x * MB;

    if (tid < 64) {
        sb1[tid] = b1[tid]; sg1[tid] = g1[tid]; sbe1[tid] = be1[tid];
        sb2[tid] = b2[tid]; sg2[tid] = g2[tid]; sbe2[tid] = be2[tid];
    }
    for (int i = tid; i < D_IN * H; i += 256) {          // Wt1[n][k] = W1[k][n]
        int k = i >> 6, n = i & 63;
        sW1t[n * 36 + k] = f2tf(W1[i]);
    }
    for (int i = tid; i < H * H; i += 256) {             // Wt2[n][k]
        int k = i >> 6, n = i & 63;
        sW2t[n * 68 + k] = f2tf(W2[i]);
    }
    for (int i = tid; i < MB * D_IN / 4; i += 256) {     // X tile, tf32, pad 36
        int r = i >> 3, c4 = i & 7;
        int node = min(base + r, N_NODES - 1);
        const float4 v = __ldg((const float4*)(x + (size_t)node * D_IN) + c4);
        sX[r * 36 + c4 * 4 + 0] = f2tf(v.x);
        sX[r * 36 + c4 * 4 + 1] = f2tf(v.y);
        sX[r * 36 + c4 * 4 + 2] = f2tf(v.z);
        sX[r * 36 + c4 * 4 + 3] = f2tf(v.w);
    }
    __syncthreads();

    const int l  = tid & 31;
    const int lr = l >> 2;          // 0..7
    const int lc = l & 3;           // 0..3
    const int r0 = (tid >> 5) * 16 + lr;   // local row (this warp's tile)

    // ---- layer 1: C1[16x64] = X[16x32] @ W1[32x64] ----
    float c1[8][4];
    #pragma unroll
    for (int nt = 0; nt < 8; nt++)
        c1[nt][0] = c1[nt][1] = c1[nt][2] = c1[nt][3] = 0.f;

    #pragma unroll
    for (int ks = 0; ks < 4; ks++) {
        const uint32_t a0 = sX[r0 * 36 + ks * 8 + lc];
        const uint32_t a1 = sX[(r0 + 8) * 36 + ks * 8 + lc];
        const uint32_t a2 = sX[r0 * 36 + ks * 8 + lc + 4];
        const uint32_t a3 = sX[(r0 + 8) * 36 + ks * 8 + lc + 4];
        #pragma unroll
        for (int nt = 0; nt < 8; nt++) {
            const uint32_t b0 = sW1t[(nt * 8 + lr) * 36 + ks * 8 + lc];
            const uint32_t b1v = sW1t[(nt * 8 + lr) * 36 + ks * 8 + lc + 4];
            mma_tf32(c1[nt], a0, a1, a2, a3, b0, b1v);
        }
    }

    // ---- LN1 + ReLU -> sHu (tf32) ----
    {
        float sl = 0.f, ql = 0.f, sh_ = 0.f, qh = 0.f;
        float v[8][4];
        #pragma unroll
        for (int nt = 0; nt < 8; nt++) {
            const int col = nt * 8 + 2 * lc;
            const float bb0 = sb1[col], bb1 = sb1[col + 1];
            v[nt][0] = c1[nt][0] + bb0; v[nt][1] = c1[nt][1] + bb1;
            v[nt][2] = c1[nt][2] + bb0; v[nt][3] = c1[nt][3] + bb1;
            sl += v[nt][0] + v[nt][1];  ql += v[nt][0]*v[nt][0] + v[nt][1]*v[nt][1];
            sh_ += v[nt][2] + v[nt][3]; qh += v[nt][2]*v[nt][2] + v[nt][3]*v[nt][3];
        }
        #pragma unroll
        for (int off = 1; off <= 2; off <<= 1) {   // quad reduce (same row)
            sl += __shfl_xor_sync(0xffffffffu, sl, off);
            ql += __shfl_xor_sync(0xffffffffu, ql, off);
            sh_ += __shfl_xor_sync(0xffffffffu, sh_, off);
            qh += __shfl_xor_sync(0xffffffffu, qh, off);
        }
        const float mul = sl * (1.0f / H), muh = sh_ * (1.0f / H);
        const float il = rsqrtf(ql * (1.0f / H) - mul * mul + 1e-5f);
        const float ih = rsqrtf(qh * (1.0f / H) - muh * muh + 1e-5f);
        #pragma unroll
        for (int nt = 0; nt < 8; nt++) {
            const int col = nt * 8 + 2 * lc;
            const float gg0 = sg1[col], gg1 = sg1[col + 1];
            const float eb0 = sbe1[col], eb1 = sbe1[col + 1];
            const float t0 = fmaxf((v[nt][0] - mul) * il * gg0 + eb0, 0.f);
            const float t1 = fmaxf((v[nt][1] - mul) * il * gg1 + eb1, 0.f);
            const float t2 = fmaxf((v[nt][2] - muh) * ih * gg0 + eb0, 0.f);
            const float t3 = fmaxf((v[nt][3] - muh) * ih * gg1 + eb1, 0.f);
            *(uint2*)&sHu[r0 * 68 + col]       = make_uint2(f2tf(t0), f2tf(t1));
            *(uint2*)&sHu[(r0 + 8) * 68 + col] = make_uint2(f2tf(t2), f2tf(t3));
        }
    }
    __syncwarp();   // warp reads only its own rows below

    // ---- layer 2: C2[16x64] = H[16x64] @ W2[64x64] ----
    float c2[8][4];
    #pragma unroll
    for (int nt = 0; nt < 8; nt++)
        c2[nt][0] = c2[nt][1] = c2[nt][2] = c2[nt][3] = 0.f;

    #pragma unroll
    for (int ks = 0; ks < 8; ks++) {
        const uint32_t a0 = sHu[r0 * 68 + ks * 8 + lc];
        const uint32_t a1 = sHu[(r0 + 8) * 68 + ks * 8 + lc];
        const uint32_t a2 = sHu[r0 * 68 + ks * 8 + lc + 4];
        const uint32_t a3 = sHu[(r0 + 8) * 68 + ks * 8 + lc + 4];
        #pragma unroll
        for (int nt = 0; nt < 8; nt++) {
            const uint32_t b0 = sW2t[(nt * 8 + lr) * 68 + ks * 8 + lc];
            const uint32_t b1v = sW2t[(nt * 8 + lr) * 68 + ks * 8 + lc + 4];
            mma_tf32(c2[nt], a0, a1, a2, a3, b0, b1v);
        }
    }

    // ---- LN2 + ReLU -> sHf (fp32 staging, overwrites tf32 h1) ----
    {
        float sl = 0.f, ql = 0.f, sh_ = 0.f, qh = 0.f;
        float v[8][4];
        #pragma unroll
        for (int nt = 0; nt < 8; nt++) {
            const int col = nt * 8 + 2 * lc;
            const float bb0 = sb2[col], bb1 = sb2[col + 1];
            v[nt][0] = c2[nt][0] + bb0; v[nt][1] = c2[nt][1] + bb1;
            v[nt][2] = c2[nt][2] + bb0; v[nt][3] = c2[nt][3] + bb1;
            sl += v[nt][0] + v[nt][1];  ql += v[nt][0]*v[nt][0] + v[nt][1]*v[nt][1];
            sh_ += v[nt][2] + v[nt][3]; qh += v[nt][2]*v[nt][2] + v[nt][3]*v[nt][3];
        }
        #pragma unroll
        for (int off = 1; off <= 2; off <<= 1) {
            sl += __shfl_xor_sync(0xffffffffu, sl, off);
            ql += __shfl_xor_sync(0xffffffffu, ql, off);
            sh_ += __shfl_xor_sync(0xffffffffu, sh_, off);
            qh += __shfl_xor_sync(0xffffffffu, qh, off);
        }
        const float mul = sl * (1.0f / H), muh = sh_ * (1.0f / H);
        const float il = rsqrtf(ql * (1.0f / H) - mul * mul + 1e-5f);
        const float ih = rsqrtf(qh * (1.0f / H) - muh * muh + 1e-5f);
        #pragma unroll
        for (int nt = 0; nt < 8; nt++) {
            const int col = nt * 8 + 2 * lc;
            const float gg0 = sg2[col], gg1 = sg2[col + 1];
            const float eb0 = sbe2[col], eb1 = sbe2[col + 1];
            const float t0 = fmaxf((v[nt][0] - mul) * il * gg0 + eb0, 0.f);
            const float t1 = fmaxf((v[nt][1] - mul) * il * gg1 + eb1, 0.f);
            const float t2 = fmaxf((v[nt][2] - muh) * ih * gg0 + eb0, 0.f);
            const float t3 = fmaxf((v[nt][3] - muh) * ih * gg1 + eb1, 0.f);
            *(float2*)&sHf[r0 * 68 + col]       = make_float2(t0, t1);
            *(float2*)&sHf[(r0 + 8) * 68 + col] = make_float2(t2, t3);
        }
    }
    __syncthreads();

    // ---- coalesced output: fp32 -> out, fp16 -> g_hh ----
    for (int i = tid; i < MB * (H / 4); i += 256) {      // 2048 float4 slots
        const int r = i >> 4, c4 = i & 15;
        const int node = base + r;
        if (node < N_NODES) {
            const float4 v = *(const float4*)&sHf[r * 68 + c4 * 4];
            ((float4*)out)[(size_t)node * 16 + c4] = v;
            const __half2 h01 = __floats2half2_rn(v.x, v.y);
            const __half2 h23 = __floats2half2_rn(v.z, v.w);
            uint2 hp;
            hp.x = *(const uint32_t*)&h01;
            hp.y = *(const uint32_t*)&h23;
            *(uint2*)(g_hh + (size_t)node * H + c4 * 4) = hp;
        }
    }
}

// ---------------------------------------------------------------------------
// K2b: degree histogram (4 edges/thread, int4 loads, fire-and-forget atomics)
// ---------------------------------------------------------------------------
__global__ __launch_bounds__(256) void hist_kernel(const int* __restrict__ ei)
{
    const int e4 = (blockIdx.x * 256 + threadIdx.x) * 4;
    if (e4 >= N_EDGES) return;
    const int4 rows = *(const int4*)&ei[e4];
    #pragma unroll
    for (int j = 0; j < 4; j++) {
        const int row = (&rows.x)[j];
        if ((unsigned)row < N_NODES) atomicAdd(&g_deg[row], 1);
    }
}

// ---------------------------------------------------------------------------
// K3b: single-kernel exclusive scan (decoupled lookback; 98 blocks all wave-1)
// ---------------------------------------------------------------------------
__global__ __launch_bounds__(SCAN_B) void scan_kernel()
{
    __shared__ int wsum[32];
    __shared__ int sprefix;
    const int t   = threadIdx.x;
    const int bid = blockIdx.x;
    const int i   = bid * SCAN_B + t;

    int v = (i < N_NODES) ? g_deg[i] : 0;
    const int orig = v;
    #pragma unroll
    for (int o = 1; o < 32; o <<= 1) {
        int n = __shfl_up_sync(0xffffffffu, v, o);
        if ((t & 31) >= o) v += n;
    }
    if ((t & 31) == 31) wsum[t >> 5] = v;
    __syncthreads();
    if (t < 32) {
        int w = wsum[t];
        #pragma unroll
        for (int o = 1; o < 32; o <<= 1) {
            int n = __shfl_up_sync(0xffffffffu, w, o);
            if (t >= o) w += n;
        }
        wsum[t] = w;
    }
    __syncthreads();
    const int base = (t >= 32) ? wsum[(t >> 5) - 1] : 0;
    const int incl = v + base;

    if (t == SCAN_B - 1) ((volatile int*)g_flag)[bid] = incl + 1;

    if (t < 32) {
        int sum = 0;
        for (int j0 = bid - 1; j0 >= 0; j0 -= 32) {
            const int j = j0 - t;
            int av = 0;
            if (j >= 0) {
                while ((av = ((volatile int*)g_flag)[j]) == 0) {}
                av -= 1;
            }
            #pragma unroll
            for (int o = 16; o > 0; o >>= 1)
                av += __shfl_xor_sync(0xffffffffu, av, o);
            sum += av;
        }
        if (t == 0) sprefix = sum;
    }
    __syncthreads();

    if (i < N_NODES) {
        const int o = sprefix + incl - orig;
        g_off[i] = o;
        g_pos[i] = o;
    }
    if (i == 0) g_off[N_NODES] = N_EDGES;
}

// ---------------------------------------------------------------------------
// K4b: scatter column ids into CSR slots (4 edges/thread, int4 index loads)
// ---------------------------------------------------------------------------
__global__ __launch_bounds__(256) void scatter_kernel(const int* __restrict__ ei)
{
    const int e4 = (blockIdx.x * 256 + threadIdx.x) * 4;
    if (e4 >= N_EDGES) return;
    const int4 rows = *(const int4*)&ei[e4];
    const int4 cols = *(const int4*)&ei[N_EDGES + e4];
    #pragma unroll
    for (int j = 0; j < 4; j++) {
        const int row = (&rows.x)[j];
        const int col = (&cols.x)[j];
        if ((unsigned)row < N_NODES) {
            int p = atomicAdd(&g_pos[row], 1);
            g_csr_col[p] = col;
        }
    }
}

// ---------------------------------------------------------------------------
// K5: pull-gather — warp per node, quarter-warp per edge (R11 structure).
// ---------------------------------------------------------------------------
__global__ __launch_bounds__(256) void gather_kernel(float* __restrict__ out)
{
    const int n = blockIdx.x * 8 + (threadIdx.x >> 5);
    if (n >= N_NODES) return;
    const int lane = threadIdx.x & 31;
    const int q  = lane >> 3;       // quarter 0..3 -> edge slot
    const int ql = lane & 7;        // position within quarter -> dim chunk

    float2 a0 = {0.f, 0.f}, a1 = {0.f, 0.f}, a2 = {0.f, 0.f}, a3 = {0.f, 0.f};

    const int start = g_off[n];
    const int end   = g_off[n + 1];

    for (int jb = start; jb < end; jb += 32) {
        const int cnt = min(32, end - jb);
        int cidx = (lane < cnt) ? g_csr_col[jb + lane] : 0;
        for (int t0 = 0; t0 < cnt; t0 += 4) {
            const int tt = t0 + q;
            const int cc = __shfl_sync(0xffffffffu, cidx, tt & 31);
            if (tt < cnt) {
                const uint4 u = __ldg((const uint4*)(g_hh + (size_t)cc * H) + ql);
                float2 f;
                f = __half22float2(*(const half2*)&u.x); a0.x += f.x; a0.y += f.y;
                f = __half22float2(*(const half2*)&u.y); a1.x += f.x; a1.y += f.y;
                f = __half22float2(*(const half2*)&u.z); a2.x += f.x; a2.y += f.y;
                f = __half22float2(*(const half2*)&u.w); a3.x += f.x; a3.y += f.y;
            }
        }
    }

    #pragma unroll
    for (int off = 8; off <= 16; off <<= 1) {
        a0.x += __shfl_xor_sync(0xffffffffu, a0.x, off);
        a0.y += __shfl_xor_sync(0xffffffffu, a0.y, off);
        a1.x += __shfl_xor_sync(0xffffffffu, a1.x, off);
        a1.y += __shfl_xor_sync(0xffffffffu, a1.y, off);
        a2.x += __shfl_xor_sync(0xffffffffu, a2.x, off);
        a2.y += __shfl_xor_sync(0xffffffffu, a2.y, off);
        a3.x += __shfl_xor_sync(0xffffffffu, a3.x, off);
        a3.y += __shfl_xor_sync(0xffffffffu, a3.y, off);
    }

    if (lane < 8) {   // q == 0 holds full sums; lane ql owns dims ql*8..+7
        float4* op = (float4*)(out + (size_t)n * H + ql * 8);
        const float4 s0 = op[0];   // exact fp32 self term (written by MLP)
        const float4 s1 = op[1];
        op[0] = make_float4(s0.x + a0.x, s0.y + a0.y, s0.z + a1.x, s0.w + a1.y);
        op[1] = make_float4(s1.x + a2.x, s1.y + a2.y, s1.z + a3.x, s1.w + a3.y);
    }
}

// ---------------------------------------------------------------------------
// inputs: x, edge_index(int32 [2,E]), W1, b1, g1, beta1, W2, b2, g2, beta2
// Two-stream fork inside graph capture: MLP on capture stream, CSR build on s2.
// ---------------------------------------------------------------------------
extern "C" void kernel_launch(void* const* d_in, const int* in_sizes, int n_in,
                              void* d_out, int out_size)
{
    const float* x   = (const float*)d_in[0];
    const int*   ei  = (const int*)d_in[1];
    const float* W1  = (const float*)d_in[2];
    const float* b1  = (const float*)d_in[3];
    const float* g1  = (const float*)d_in[4];
    const float* be1 = (const float*)d_in[5];
    const float* W2  = (const float*)d_in[6];
    const float* b2  = (const float*)d_in[7];
    const float* g2  = (const float*)d_in[8];
    const float* be2 = (const float*)d_in[9];
    float* out = (float*)d_out;

    static cudaStream_t s2 = nullptr;
    static cudaEvent_t evFork = nullptr, evJoin = nullptr;
    static void* p_deg = nullptr;
    static void* p_flag = nullptr;
    if (!s2) {
        cudaStreamCreateWithFlags(&s2, cudaStreamNonBlocking);
        cudaEventCreateWithFlags(&evFork, cudaEventDisableTiming);
        cudaEventCreateWithFlags(&evJoin, cudaEventDisableTiming);
        cudaGetSymbolAddress(&p_deg,  g_deg);
        cudaGetSymbolAddress(&p_flag, g_flag);
        cudaFuncSetAttribute(mlp_kernel,
                             cudaFuncAttributeMaxDynamicSharedMemorySize,
                             SMEM_TOTAL);
    }

    cudaEventRecord(evFork, 0);
    cudaStreamWaitEvent(s2, evFork, 0);

    cudaMemsetAsync(p_deg,  0, sizeof(int) * N_NODES, s2);
    cudaMemsetAsync(p_flag, 0, sizeof(int) * NB, s2);
    hist_kernel<<<(N_EDGES / 4 + 255) / 256, 256, 0, s2>>>(ei);
    scan_kernel<<<NB, SCAN_B, 0, s2>>>();
    scatter_kernel<<<(N_EDGES / 4 + 255) / 256, 256, 0, s2>>>(ei);
    cudaEventRecord(evJoin, s2);

    mlp_kernel<<<MLPB, 256, SMEM_TOTAL>>>(x, W1, b1, g1, be1, W2, b2, g2, be2, out);

    cudaStreamWaitEvent(0, evJoin, 0);
    gather_kernel<<<(N_NODES + 7) / 8, 256>>>(out);
}

// round 14
// speedup vs baseline: 1.3036x; 1.1471x over previous
#include <cuda_runtime.h>
#include <cuda_fp16.h>
#include <cstdint>

#define N_NODES 100000
#define N_EDGES 1250000
#define D_IN 32
#define H 64
#define SCAN_B 1024
#define NB ((N_NODES + SCAN_B - 1) / SCAN_B)   // 98
#define MB 128                                  // nodes per tile (MLP)
#define NTILES ((N_NODES + MB - 1) / MB)        // 782 tiles
#define MLP_GRID 296                            // 2 blocks/SM, persistent

// SMEM layout (bytes) for mlp_kernel
#define OFF_X   0                               // uint32 tf32 [128][36]
#define OFF_W1  (OFF_X  + 128 * 36 * 4)         // uint32 tf32 Wt1 [64][36]
#define OFF_W2  (OFF_W1 + 64 * 36 * 4)          // uint32 tf32 Wt2 [64][68]
#define OFF_H   (OFF_W2 + 64 * 68 * 4)          // tf32 then fp32 [128][68]
#define OFF_P   (OFF_H  + 128 * 68 * 4)         // 6 x 64 fp32 params
#define SMEM_TOTAL (OFF_P + 6 * 64 * 4)

// scratch
__device__ __half g_hh[(size_t)N_NODES * H];    // fp16 copy of h (gather source)
__device__ int    g_deg[N_NODES];
__device__ int    g_off[N_NODES + 1];
__device__ int    g_pos[N_NODES];
__device__ int    g_csr_col[N_EDGES];
__device__ int    g_flag[NB];                   // decoupled-lookback: agg+1 (0 = not ready)

__device__ __forceinline__ uint32_t f2tf(float f) {
    uint32_t r;
    asm("cvt.rna.tf32.f32 %0, %1;" : "=r"(r) : "f"(f));
    return r;
}

__device__ __forceinline__ void mma_tf32(float* c, uint32_t a0, uint32_t a1,
                                         uint32_t a2, uint32_t a3,
                                         uint32_t b0, uint32_t b1) {
    asm volatile(
        "mma.sync.aligned.m16n8k8.row.col.f32.tf32.tf32.f32 "
        "{%0,%1,%2,%3}, {%4,%5,%6,%7}, {%8,%9}, {%0,%1,%2,%3};"
        : "+f"(c[0]), "+f"(c[1]), "+f"(c[2]), "+f"(c[3])
        : "r"(a0), "r"(a1), "r"(a2), "r"(a3), "r"(b0), "r"(b1));
}

// ---------------------------------------------------------------------------
// K1: persistent tensor-core MLP.  Grid = 296 (2 blocks/SM); each block stages
// weights ONCE, then loops over 128-node tiles (tile = bid, bid+296, ...).
// Warp = m16 row tile; m16n8k8 tf32 mma; LN in-fragment (quad shfl).
// ---------------------------------------------------------------------------
__global__ __launch_bounds__(256, 2) void mlp_kernel(
    const float* __restrict__ x,
    const float* __restrict__ W1, const float* __restrict__ b1,
    const float* __restrict__ g1, const float* __restrict__ be1,
    const float* __restrict__ W2, const float* __restrict__ b2,
    const float* __restrict__ g2, const float* __restrict__ be2,
    float* __restrict__ out)
{
    extern __shared__ char smem[];
    uint32_t* sX   = (uint32_t*)(smem + OFF_X);    // [128][36]
    uint32_t* sW1t = (uint32_t*)(smem + OFF_W1);   // [64][36]  Wt1[n][k]
    uint32_t* sW2t = (uint32_t*)(smem + OFF_W2);   // [64][68]  Wt2[n][k]
    uint32_t* sHu  = (uint32_t*)(smem + OFF_H);    // [128][68] tf32 h1
    float*    sHf  = (float*)   (smem + OFF_H);    // reused as fp32 out staging
    float*    sb1  = (float*)(smem + OFF_P);
    float*    sg1  = sb1 + 64;
    float*    sbe1 = sb1 + 128;
    float*    sb2  = sb1 + 192;
    float*    sg2  = sb1 + 256;
    float*    sbe2 = sb1 + 320;

    const int tid = threadIdx.x;

    // ---- one-time staging: weights + params ----
    if (tid < 64) {
        sb1[tid] = b1[tid]; sg1[tid] = g1[tid]; sbe1[tid] = be1[tid];
        sb2[tid] = b2[tid]; sg2[tid] = g2[tid]; sbe2[tid] = be2[tid];
    }
    for (int i = tid; i < D_IN * H; i += 256) {          // Wt1[n][k] = W1[k][n]
        int k = i >> 6, n = i & 63;
        sW1t[n * 36 + k] = f2tf(W1[i]);
    }
    for (int i = tid; i < H * H; i += 256) {             // Wt2[n][k]
        int k = i >> 6, n = i & 63;
        sW2t[n * 68 + k] = f2tf(W2[i]);
    }

    const int l  = tid & 31;
    const int lr = l >> 2;          // 0..7
    const int lc = l & 3;           // 0..3
    const int r0 = (tid >> 5) * 16 + lr;   // local row (this warp's tile)

    for (int tile = blockIdx.x; tile < NTILES; tile += MLP_GRID) {
        const int base = tile * MB;

        // stage X tile (tf32, pad 36)
        for (int i = tid; i < MB * D_IN / 4; i += 256) {
            int r = i >> 3, c4 = i & 7;
            int node = min(base + r, N_NODES - 1);
            const float4 v = __ldg((const float4*)(x + (size_t)node * D_IN) + c4);
            sX[r * 36 + c4 * 4 + 0] = f2tf(v.x);
            sX[r * 36 + c4 * 4 + 1] = f2tf(v.y);
            sX[r * 36 + c4 * 4 + 2] = f2tf(v.z);
            sX[r * 36 + c4 * 4 + 3] = f2tf(v.w);
        }
        __syncthreads();   // X ready; also fences prev tile's sHf reads vs sHu writes

        // ---- layer 1: C1[16x64] = X[16x32] @ W1[32x64] ----
        float c1[8][4];
        #pragma unroll
        for (int nt = 0; nt < 8; nt++)
            c1[nt][0] = c1[nt][1] = c1[nt][2] = c1[nt][3] = 0.f;

        #pragma unroll
        for (int ks = 0; ks < 4; ks++) {
            const uint32_t a0 = sX[r0 * 36 + ks * 8 + lc];
            const uint32_t a1 = sX[(r0 + 8) * 36 + ks * 8 + lc];
            const uint32_t a2 = sX[r0 * 36 + ks * 8 + lc + 4];
            const uint32_t a3 = sX[(r0 + 8) * 36 + ks * 8 + lc + 4];
            #pragma unroll
            for (int nt = 0; nt < 8; nt++) {
                const uint32_t b0  = sW1t[(nt * 8 + lr) * 36 + ks * 8 + lc];
                const uint32_t b1v = sW1t[(nt * 8 + lr) * 36 + ks * 8 + lc + 4];
                mma_tf32(c1[nt], a0, a1, a2, a3, b0, b1v);
            }
        }

        // ---- LN1 + ReLU -> sHu (tf32) ----
        {
            float sl = 0.f, ql = 0.f, sh_ = 0.f, qh = 0.f;
            float v[8][4];
            #pragma unroll
            for (int nt = 0; nt < 8; nt++) {
                const int col = nt * 8 + 2 * lc;
                const float bb0 = sb1[col], bb1 = sb1[col + 1];
                v[nt][0] = c1[nt][0] + bb0; v[nt][1] = c1[nt][1] + bb1;
                v[nt][2] = c1[nt][2] + bb0; v[nt][3] = c1[nt][3] + bb1;
                sl += v[nt][0] + v[nt][1];  ql += v[nt][0]*v[nt][0] + v[nt][1]*v[nt][1];
                sh_ += v[nt][2] + v[nt][3]; qh += v[nt][2]*v[nt][2] + v[nt][3]*v[nt][3];
            }
            #pragma unroll
            for (int off = 1; off <= 2; off <<= 1) {
                sl += __shfl_xor_sync(0xffffffffu, sl, off);
                ql += __shfl_xor_sync(0xffffffffu, ql, off);
                sh_ += __shfl_xor_sync(0xffffffffu, sh_, off);
                qh += __shfl_xor_sync(0xffffffffu, qh, off);
            }
            const float mul = sl * (1.0f / H), muh = sh_ * (1.0f / H);
            const float il = rsqrtf(ql * (1.0f / H) - mul * mul + 1e-5f);
            const float ih = rsqrtf(qh * (1.0f / H) - muh * muh + 1e-5f);
            #pragma unroll
            for (int nt = 0; nt < 8; nt++) {
                const int col = nt * 8 + 2 * lc;
                const float gg0 = sg1[col], gg1 = sg1[col + 1];
                const float eb0 = sbe1[col], eb1 = sbe1[col + 1];
                const float t0 = fmaxf((v[nt][0] - mul) * il * gg0 + eb0, 0.f);
                const float t1 = fmaxf((v[nt][1] - mul) * il * gg1 + eb1, 0.f);
                const float t2 = fmaxf((v[nt][2] - muh) * ih * gg0 + eb0, 0.f);
                const float t3 = fmaxf((v[nt][3] - muh) * ih * gg1 + eb1, 0.f);
                *(uint2*)&sHu[r0 * 68 + col]       = make_uint2(f2tf(t0), f2tf(t1));
                *(uint2*)&sHu[(r0 + 8) * 68 + col] = make_uint2(f2tf(t2), f2tf(t3));
            }
        }
        __syncwarp();   // warp reads only its own rows below

        // ---- layer 2: C2[16x64] = H[16x64] @ W2[64x64] ----
        float c2[8][4];
        #pragma unroll
        for (int nt = 0; nt < 8; nt++)
            c2[nt][0] = c2[nt][1] = c2[nt][2] = c2[nt][3] = 0.f;

        #pragma unroll
        for (int ks = 0; ks < 8; ks++) {
            const uint32_t a0 = sHu[r0 * 68 + ks * 8 + lc];
            const uint32_t a1 = sHu[(r0 + 8) * 68 + ks * 8 + lc];
            const uint32_t a2 = sHu[r0 * 68 + ks * 8 + lc + 4];
            const uint32_t a3 = sHu[(r0 + 8) * 68 + ks * 8 + lc + 4];
            #pragma unroll
            for (int nt = 0; nt < 8; nt++) {
                const uint32_t b0  = sW2t[(nt * 8 + lr) * 68 + ks * 8 + lc];
                const uint32_t b1v = sW2t[(nt * 8 + lr) * 68 + ks * 8 + lc + 4];
                mma_tf32(c2[nt], a0, a1, a2, a3, b0, b1v);
            }
        }

        // ---- LN2 + ReLU -> sHf (fp32 staging; overwrites tf32 h1) ----
        {
            float sl = 0.f, ql = 0.f, sh_ = 0.f, qh = 0.f;
            float v[8][4];
            #pragma unroll
            for (int nt = 0; nt < 8; nt++) {
                const int col = nt * 8 + 2 * lc;
                const float bb0 = sb2[col], bb1 = sb2[col + 1];
                v[nt][0] = c2[nt][0] + bb0; v[nt][1] = c2[nt][1] + bb1;
                v[nt][2] = c2[nt][2] + bb0; v[nt][3] = c2[nt][3] + bb1;
                sl += v[nt][0] + v[nt][1];  ql += v[nt][0]*v[nt][0] + v[nt][1]*v[nt][1];
                sh_ += v[nt][2] + v[nt][3]; qh += v[nt][2]*v[nt][2] + v[nt][3]*v[nt][3];
            }
            #pragma unroll
            for (int off = 1; off <= 2; off <<= 1) {
                sl += __shfl_xor_sync(0xffffffffu, sl, off);
                ql += __shfl_xor_sync(0xffffffffu, ql, off);
                sh_ += __shfl_xor_sync(0xffffffffu, sh_, off);
                qh += __shfl_xor_sync(0xffffffffu, qh, off);
            }
            const float mul = sl * (1.0f / H), muh = sh_ * (1.0f / H);
            const float il = rsqrtf(ql * (1.0f / H) - mul * mul + 1e-5f);
            const float ih = rsqrtf(qh * (1.0f / H) - muh * muh + 1e-5f);
            #pragma unroll
            for (int nt = 0; nt < 8; nt++) {
                const int col = nt * 8 + 2 * lc;
                const float gg0 = sg2[col], gg1 = sg2[col + 1];
                const float eb0 = sbe2[col], eb1 = sbe2[col + 1];
                const float t0 = fmaxf((v[nt][0] - mul) * il * gg0 + eb0, 0.f);
                const float t1 = fmaxf((v[nt][1] - mul) * il * gg1 + eb1, 0.f);
                const float t2 = fmaxf((v[nt][2] - muh) * ih * gg0 + eb0, 0.f);
                const float t3 = fmaxf((v[nt][3] - muh) * ih * gg1 + eb1, 0.f);
                *(float2*)&sHf[r0 * 68 + col]       = make_float2(t0, t1);
                *(float2*)&sHf[(r0 + 8) * 68 + col] = make_float2(t2, t3);
            }
        }
        __syncthreads();

        // ---- coalesced output: fp32 -> out, fp16 -> g_hh ----
        for (int i = tid; i < MB * (H / 4); i += 256) {
            const int r = i >> 4, c4 = i & 15;
            const int node = base + r;
            if (node < N_NODES) {
                const float4 v = *(const float4*)&sHf[r * 68 + c4 * 4];
                ((float4*)out)[(size_t)node * 16 + c4] = v;
                const __half2 h01 = __floats2half2_rn(v.x, v.y);
                const __half2 h23 = __floats2half2_rn(v.z, v.w);
                uint2 hp;
                hp.x = *(const uint32_t*)&h01;
                hp.y = *(const uint32_t*)&h23;
                *(uint2*)(g_hh + (size_t)node * H + c4 * 4) = hp;
            }
        }
        // next iteration's __syncthreads (after X stage) fences sHf reads
    }
}

// ---------------------------------------------------------------------------
// K2b: degree histogram (4 edges/thread, int4 loads, fire-and-forget atomics)
// ---------------------------------------------------------------------------
__global__ __launch_bounds__(256) void hist_kernel(const int* __restrict__ ei)
{
    const int e4 = (blockIdx.x * 256 + threadIdx.x) * 4;
    if (e4 >= N_EDGES) return;
    const int4 rows = *(const int4*)&ei[e4];
    #pragma unroll
    for (int j = 0; j < 4; j++) {
        const int row = (&rows.x)[j];
        if ((unsigned)row < N_NODES) atomicAdd(&g_deg[row], 1);
    }
}

// ---------------------------------------------------------------------------
// K3b: single-kernel exclusive scan (decoupled lookback; 98 blocks all wave-1)
// ---------------------------------------------------------------------------
__global__ __launch_bounds__(SCAN_B) void scan_kernel()
{
    __shared__ int wsum[32];
    __shared__ int sprefix;
    const int t   = threadIdx.x;
    const int bid = blockIdx.x;
    const int i   = bid * SCAN_B + t;

    int v = (i < N_NODES) ? g_deg[i] : 0;
    const int orig = v;
    #pragma unroll
    for (int o = 1; o < 32; o <<= 1) {
        int n = __shfl_up_sync(0xffffffffu, v, o);
        if ((t & 31) >= o) v += n;
    }
    if ((t & 31) == 31) wsum[t >> 5] = v;
    __syncthreads();
    if (t < 32) {
        int w = wsum[t];
        #pragma unroll
        for (int o = 1; o < 32; o <<= 1) {
            int n = __shfl_up_sync(0xffffffffu, w, o);
            if (t >= o) w += n;
        }
        wsum[t] = w;
    }
    __syncthreads();
    const int base = (t >= 32) ? wsum[(t >> 5) - 1] : 0;
    const int incl = v + base;

    if (t == SCAN_B - 1) ((volatile int*)g_flag)[bid] = incl + 1;

    if (t < 32) {
        int sum = 0;
        for (int j0 = bid - 1; j0 >= 0; j0 -= 32) {
            const int j = j0 - t;
            int av = 0;
            if (j >= 0) {
                while ((av = ((volatile int*)g_flag)[j]) == 0) {}
                av -= 1;
            }
            #pragma unroll
            for (int o = 16; o > 0; o >>= 1)
                av += __shfl_xor_sync(0xffffffffu, av, o);
            sum += av;
        }
        if (t == 0) sprefix = sum;
    }
    __syncthreads();

    if (i < N_NODES) {
        const int o = sprefix + incl - orig;
        g_off[i] = o;
        g_pos[i] = o;
    }
    if (i == 0) g_off[N_NODES] = N_EDGES;
}

// ---------------------------------------------------------------------------
// K4b: scatter column ids into CSR slots (4 edges/thread, int4 index loads)
// ---------------------------------------------------------------------------
__global__ __launch_bounds__(256) void scatter_kernel(const int* __restrict__ ei)
{
    const int e4 = (blockIdx.x * 256 + threadIdx.x) * 4;
    if (e4 >= N_EDGES) return;
    const int4 rows = *(const int4*)&ei[e4];
    const int4 cols = *(const int4*)&ei[N_EDGES + e4];
    #pragma unroll
    for (int j = 0; j < 4; j++) {
        const int row = (&rows.x)[j];
        const int col = (&cols.x)[j];
        if ((unsigned)row < N_NODES) {
            int p = atomicAdd(&g_pos[row], 1);
            g_csr_col[p] = col;
        }
    }
}

// ---------------------------------------------------------------------------
// K5: pull-gather — warp per node, quarter-warp per edge (R11 structure).
// ---------------------------------------------------------------------------
__global__ __launch_bounds__(256) void gather_kernel(float* __restrict__ out)
{
    const int n = blockIdx.x * 8 + (threadIdx.x >> 5);
    if (n >= N_NODES) return;
    const int lane = threadIdx.x & 31;
    const int q  = lane >> 3;       // quarter 0..3 -> edge slot
    const int ql = lane & 7;        // position within quarter -> dim chunk

    float2 a0 = {0.f, 0.f}, a1 = {0.f, 0.f}, a2 = {0.f, 0.f}, a3 = {0.f, 0.f};

    const int start = g_off[n];
    const int end   = g_off[n + 1];

    for (int jb = start; jb < end; jb += 32) {
        const int cnt = min(32, end - jb);
        int cidx = (lane < cnt) ? g_csr_col[jb + lane] : 0;
        for (int t0 = 0; t0 < cnt; t0 += 4) {
            const int tt = t0 + q;
            const int cc = __shfl_sync(0xffffffffu, cidx, tt & 31);
            if (tt < cnt) {
                const uint4 u = __ldg((const uint4*)(g_hh + (size_t)cc * H) + ql);
                float2 f;
                f = __half22float2(*(const half2*)&u.x); a0.x += f.x; a0.y += f.y;
                f = __half22float2(*(const half2*)&u.y); a1.x += f.x; a1.y += f.y;
                f = __half22float2(*(const half2*)&u.z); a2.x += f.x; a2.y += f.y;
                f = __half22float2(*(const half2*)&u.w); a3.x += f.x; a3.y += f.y;
            }
        }
    }

    #pragma unroll
    for (int off = 8; off <= 16; off <<= 1) {
        a0.x += __shfl_xor_sync(0xffffffffu, a0.x, off);
        a0.y += __shfl_xor_sync(0xffffffffu, a0.y, off);
        a1.x += __shfl_xor_sync(0xffffffffu, a1.x, off);
        a1.y += __shfl_xor_sync(0xffffffffu, a1.y, off);
        a2.x += __shfl_xor_sync(0xffffffffu, a2.x, off);
        a2.y += __shfl_xor_sync(0xffffffffu, a2.y, off);
        a3.x += __shfl_xor_sync(0xffffffffu, a3.x, off);
        a3.y += __shfl_xor_sync(0xffffffffu, a3.y, off);
    }

    if (lane < 8) {   // q == 0 holds full sums; lane ql owns dims ql*8..+7
        float4* op = (float4*)(out + (size_t)n * H + ql * 8);
        const float4 s0 = op[0];   // exact fp32 self term (written by MLP)
        const float4 s1 = op[1];
        op[0] = make_float4(s0.x + a0.x, s0.y + a0.y, s0.z + a1.x, s0.w + a1.y);
        op[1] = make_float4(s1.x + a2.x, s1.y + a2.y, s1.z + a3.x, s1.w + a3.y);
    }
}

// ---------------------------------------------------------------------------
// inputs: x, edge_index(int32 [2,E]), W1, b1, g1, beta1, W2, b2, g2, beta2
// Two-stream fork inside graph capture: MLP on capture stream, CSR build on s2.
// ---------------------------------------------------------------------------
extern "C" void kernel_launch(void* const* d_in, const int* in_sizes, int n_in,
                              void* d_out, int out_size)
{
    const float* x   = (const float*)d_in[0];
    const int*   ei  = (const int*)d_in[1];
    const float* W1  = (const float*)d_in[2];
    const float* b1  = (const float*)d_in[3];
    const float* g1  = (const float*)d_in[4];
    const float* be1 = (const float*)d_in[5];
    const float* W2  = (const float*)d_in[6];
    const float* b2  = (const float*)d_in[7];
    const float* g2  = (const float*)d_in[8];
    const float* be2 = (const float*)d_in[9];
    float* out = (float*)d_out;

    static cudaStream_t s2 = nullptr;
    static cudaEvent_t evFork = nullptr, evJoin = nullptr;
    static void* p_deg = nullptr;
    static void* p_flag = nullptr;
    if (!s2) {
        cudaStreamCreateWithFlags(&s2, cudaStreamNonBlocking);
        cudaEventCreateWithFlags(&evFork, cudaEventDisableTiming);
        cudaEventCreateWithFlags(&evJoin, cudaEventDisableTiming);
        cudaGetSymbolAddress(&p_deg,  g_deg);
        cudaGetSymbolAddress(&p_flag, g_flag);
        cudaFuncSetAttribute(mlp_kernel,
                             cudaFuncAttributeMaxDynamicSharedMemorySize,
                             SMEM_TOTAL);
    }

    cudaEventRecord(evFork, 0);
    cudaStreamWaitEvent(s2, evFork, 0);

    cudaMemsetAsync(p_deg,  0, sizeof(int) * N_NODES, s2);
    cudaMemsetAsync(p_flag, 0, sizeof(int) * NB, s2);
    hist_kernel<<<(N_EDGES / 4 + 255) / 256, 256, 0, s2>>>(ei);
    scan_kernel<<<NB, SCAN_B, 0, s2>>>();
    scatter_kernel<<<(N_EDGES / 4 + 255) / 256, 256, 0, s2>>>(ei);
    cudaEventRecord(evJoin, s2);

    mlp_kernel<<<MLP_GRID, 256, SMEM_TOTAL>>>(x, W1, b1, g1, be1, W2, b2, g2, be2, out);

    cudaStreamWaitEvent(0, evJoin, 0);
    gather_kernel<<<(N_NODES + 7) / 8, 256>>>(out);
}